// round 1
// baseline (speedup 1.0000x reference)
#include <cuda_runtime.h>

#define NN 1024
#define BB 4
#define HH 32

// 4 MB scratch for the normalized, diagonal-masked softmax adjacency.
__device__ float g_A[NN * NN];

// ---------------- packed f32x2 helpers (sm_100+) ----------------
static __device__ __forceinline__ unsigned long long pack2(float lo, float hi) {
    unsigned long long r;
    asm("mov.b64 %0, {%1, %2};" : "=l"(r) : "f"(lo), "f"(hi));
    return r;
}
static __device__ __forceinline__ void unpack2(unsigned long long v, float& lo, float& hi) {
    asm("mov.b64 {%0, %1}, %2;" : "=f"(lo), "=f"(hi) : "l"(v));
}
static __device__ __forceinline__ unsigned long long fma2(unsigned long long a,
                                                          unsigned long long b,
                                                          unsigned long long c) {
    unsigned long long d;
    asm("fma.rn.f32x2 %0, %1, %2, %3;" : "=l"(d) : "l"(a), "l"(b), "l"(c));
    return d;
}
static __device__ __forceinline__ unsigned long long add2(unsigned long long a,
                                                          unsigned long long b) {
    unsigned long long d;
    asm("add.rn.f32x2 %0, %1, %2;" : "=l"(d) : "l"(a), "l"(b));
    return d;
}
static __device__ __forceinline__ float tanhx(float x) {
    float y;
    asm("tanh.approx.f32 %0, %1;" : "=f"(y) : "f"(x));
    return y;
}
static __device__ __forceinline__ unsigned long long tanh2(unsigned long long v) {
    float lo, hi;
    unpack2(v, lo, hi);
    return pack2(tanhx(lo), tanhx(hi));
}

// ---------------- Kernel 1: masked row softmax of Theta -> g_A ----------------
// A[i,j] = exp(Theta[i,j]-m_i) / sum_{k != i} exp(Theta[i,k]-m_i), A[i,i] = 0.
// (softmax + zero-diag + renormalize == softmax over off-diagonal entries)
__global__ __launch_bounds__(256) void softmax_kernel(const float* __restrict__ Theta) {
    int i = blockIdx.x;
    int t = threadIdx.x;
    const float* row = Theta + (size_t)i * NN;

    float vals[4];
    float m = -3.4e38f;
#pragma unroll
    for (int u = 0; u < 4; u++) {
        vals[u] = row[t + 256 * u];
        m = fmaxf(m, vals[u]);
    }
#pragma unroll
    for (int o = 16; o; o >>= 1) m = fmaxf(m, __shfl_xor_sync(0xffffffffu, m, o));

    __shared__ float redmax[8], redsum[8];
    if ((t & 31) == 0) redmax[t >> 5] = m;
    __syncthreads();
    float m0 = redmax[0];
#pragma unroll
    for (int w = 1; w < 8; w++) m0 = fmaxf(m0, redmax[w]);

    float s = 0.f;
#pragma unroll
    for (int u = 0; u < 4; u++) {
        int j = t + 256 * u;
        float e = __expf(vals[u] - m0);
        if (j == i) e = 0.f;
        vals[u] = e;
        s += e;
    }
#pragma unroll
    for (int o = 16; o; o >>= 1) s += __shfl_xor_sync(0xffffffffu, s, o);
    if ((t & 31) == 0) redsum[t >> 5] = s;
    __syncthreads();
    float tot = 0.f;
#pragma unroll
    for (int w = 0; w < 8; w++) tot += redsum[w];
    float inv = 1.0f / tot;
#pragma unroll
    for (int u = 0; u < 4; u++) g_A[(size_t)i * NN + t + 256 * u] = vals[u] * inv;
}

// ---------------- Kernel 2: pairwise MLP gate + aggregation ----------------
// One block per (b, i). 256 threads, 4 j's per thread as 2 packed f32x2 units.
__global__ __launch_bounds__(256, 1) void agg_kernel(
    const float* __restrict__ x,
    const float* __restrict__ W1, const float* __restrict__ b1,
    const float* __restrict__ W2, const float* __restrict__ b2,
    const float* __restrict__ W3, const float* __restrict__ b3,
    float* __restrict__ out) {
    // W2 duplicated into both f32x2 lanes; rows 256B -> every row 16B aligned.
    __shared__ __align__(16) unsigned long long sW2[HH][HH];
    __shared__ unsigned long long sC0[HH];   // (W1[m][0]-W1[m][2])*xi + b1[m]   (dup)
    __shared__ unsigned long long sW12[HH];  // W1[m][1]+W1[m][2]                (dup)
    __shared__ unsigned long long sB2[HH];   // b2[m]                            (dup)
    __shared__ unsigned long long sW3[HH];   // W3[0][m]                         (dup)
    __shared__ float warpsum[8];

    int t = threadIdx.x;
    int bi = blockIdx.x;
    int b = bi >> 10;
    int i = bi & (NN - 1);
    const float* xb = x + b * NN;
    float xi = xb[i];

    for (int idx = t; idx < HH * HH; idx += 256) {
        float w = W2[idx];
        sW2[idx >> 5][idx & 31] = pack2(w, w);
    }
    if (t < HH) {
        int m = t;
        float w0 = W1[3 * m + 0];
        float w1v = W1[3 * m + 1];
        float w2v = W1[3 * m + 2];
        float c0 = fmaf(w0 - w2v, xi, b1[m]);
        sC0[m] = pack2(c0, c0);
        float w12 = w1v + w2v;
        sW12[m] = pack2(w12, w12);
        float bb = b2[m];
        sB2[m] = pack2(bb, bb);
        float w3 = W3[m];
        sW3[m] = pack2(w3, w3);
    }
    __syncthreads();

    int j0 = t, j1 = t + 256, j2 = t + 512, j3 = t + 768;
    float xj0 = xb[j0], xj1 = xb[j1], xj2 = xb[j2], xj3 = xb[j3];
    unsigned long long xjA = pack2(xj0, xj1);
    unsigned long long xjB = pack2(xj2, xj3);

    // Layer 1: h1[m] = tanh( c0[m] + (w1+w2)[m] * xj )   [feats folded]
    unsigned long long h1A[HH], h1B[HH];
#pragma unroll
    for (int m = 0; m < HH; m++) {
        unsigned long long w = sW12[m];
        unsigned long long c = sC0[m];
        h1A[m] = tanh2(fma2(xjA, w, c));
        h1B[m] = tanh2(fma2(xjB, w, c));
    }

    // Layers 2+3 fused: raw += W3[m] * tanh(b2[m] + sum_k h1[k]*W2[m][k])
    float b3v = b3[0];
    unsigned long long rawA = pack2(b3v, b3v);
    unsigned long long rawB = rawA;
    const unsigned long long zero2 = pack2(0.f, 0.f);

#pragma unroll 2
    for (int m = 0; m < HH; m++) {
        const ulonglong2* wr = reinterpret_cast<const ulonglong2*>(&sW2[m][0]);
        unsigned long long aA0 = sB2[m];
        unsigned long long aB0 = aA0;
        unsigned long long aA1 = zero2;
        unsigned long long aB1 = zero2;
#pragma unroll
        for (int k2 = 0; k2 < HH / 2; k2++) {
            ulonglong2 w = wr[k2];  // LDS.128: W2[m][2k],W2[m][2k+1] both-lane dup
            aA0 = fma2(h1A[2 * k2], w.x, aA0);
            aB0 = fma2(h1B[2 * k2], w.x, aB0);
            aA1 = fma2(h1A[2 * k2 + 1], w.y, aA1);
            aB1 = fma2(h1B[2 * k2 + 1], w.y, aB1);
        }
        unsigned long long hA = tanh2(add2(aA0, aA1));
        unsigned long long hB = tanh2(add2(aB0, aB1));
        unsigned long long w3 = sW3[m];
        rawA = fma2(hA, w3, rawA);
        rawB = fma2(hB, w3, rawB);
    }

    // alpha = 2*sigmoid(raw) = 1 + tanh(raw/2)    (ALPHA_MIN=0, ALPHA_MAX=2)
    float rA0, rA1, rB0, rB1;
    unpack2(rawA, rA0, rA1);
    unpack2(rawB, rB0, rB1);
    float al0 = 1.f + tanhx(0.5f * rA0);
    float al1 = 1.f + tanhx(0.5f * rA1);
    float al2 = 1.f + tanhx(0.5f * rB0);
    float al3 = 1.f + tanhx(0.5f * rB1);

    // A[i,i] = 0 and diff(i,i) = 0, so no diagonal special-casing needed.
    const float* Ar = g_A + (size_t)i * NN;
    float acc = Ar[j0] * al0 * (xj0 - xi)
              + Ar[j1] * al1 * (xj1 - xi)
              + Ar[j2] * al2 * (xj2 - xi)
              + Ar[j3] * al3 * (xj3 - xi);

    // block reduction over 256 threads
#pragma unroll
    for (int o = 16; o; o >>= 1) acc += __shfl_xor_sync(0xffffffffu, acc, o);
    if ((t & 31) == 0) warpsum[t >> 5] = acc;
    __syncthreads();
    if (t == 0) {
        float s = 0.f;
#pragma unroll
        for (int w = 0; w < 8; w++) s += warpsum[w];
        out[b * NN + i] = fmaf(0.1f, s, xi);
    }
}

extern "C" void kernel_launch(void* const* d_in, const int* in_sizes, int n_in,
                              void* d_out, int out_size) {
    (void)in_sizes; (void)n_in; (void)out_size;
    const float* x  = (const float*)d_in[0];
    const float* Th = (const float*)d_in[1];
    const float* W1 = (const float*)d_in[2];
    const float* b1 = (const float*)d_in[3];
    const float* W2 = (const float*)d_in[4];
    const float* b2 = (const float*)d_in[5];
    const float* W3 = (const float*)d_in[6];
    const float* b3 = (const float*)d_in[7];
    float* out = (float*)d_out;

    softmax_kernel<<<NN, 256>>>(Th);
    agg_kernel<<<BB * NN, 256>>>(x, W1, b1, W2, b2, W3, b3, out);
}